// round 7
// baseline (speedup 1.0000x reference)
#include <cuda_runtime.h>
#include <cuda_bf16.h>

// Problem constants
#define B_   65536
#define NS_  8
#define G_   8
#define E_   16

#define THREADS_ 384
#define ROWS_    96            // rows per tile (4 threads per row)
#define NTILES_  683           // ceil(65536/96)
#define GRID_    152

// ---- shared memory layout (float offsets) ----
#define O_W1B1  0        // [n][e]{W1,b1}                2048
#define O_W2T   2048     // [n][e][f]                    16384
#define O_B2    18432    // [n][f]                       1024
#define O_QKVS  19456    // [s][e][48]  (q-part *0.5)    6144
#define O_BQKVS 25600    // [s][48]     (q-part *0.5)    384
#define O_MF    25984    // [s][t][ep][f] fused Wo*Wsys  16384
#define O_CF    42368    // [s][f]                       128
#define O_QKVX  42496    // [e][48]     (q-part *0.5)    768
#define O_BQKVX 43264    // [48]        (q-part *0.5)    48
#define O_WOX   43312    // [e][f]                       256
#define O_BOX   43568    // [f]                          16
#define O_SIDX  43584    // 64 ints                      64
#define O_EB    43648    // 96 rows x SROW token scratch
#define SROW_   132
#define SMEM_FLOATS (O_EB + ROWS_ * SROW_)   // 56320
#define SMEM_BYTES  (SMEM_FLOATS * 4)        // 225280

// fused out-proj * system-embedding weights (per-launch precompute)
__device__ float g_M[NS_ * G_ * E_ * E_];   // [s][t][ep][f]
__device__ float g_C[NS_ * E_];             // [s][f]
// fallback scratch for system embeddings if out buffer lacks the all_sys region
__device__ float g_SE[(size_t)B_ * 128];

#define LD4(dst, p) { float4 _t = *(const float4*)(p); \
    (dst)[0]=_t.x; (dst)[1]=_t.y; (dst)[2]=_t.z; (dst)[3]=_t.w; }
#define ST4(p, src) { *(float4*)(p) = make_float4((src)[0],(src)[1],(src)[2],(src)[3]); }

// ---------------------------------------------------------------------------
// Prep: M[s][t][ep][f] = sum_e Wo_s[s][e][ep] * Wsys[s][f][t*16+e]
//       C[s][f]        = bsys[s][f] + sum_{t,e} bo_s[s][e]*Wsys[s][f][t*16+e]
// ---------------------------------------------------------------------------
__global__ void bio_prep_kernel(const float* __restrict__ Wo_s,
                                const float* __restrict__ Wsys,
                                const float* __restrict__ bo_s,
                                const float* __restrict__ bsys)
{
    int idx = blockIdx.x * blockDim.x + threadIdx.x;   // 0..16383
    int s  = idx >> 11;
    int r  = idx & 2047;
    int t  = r >> 8;
    int ep = (r >> 4) & 15;
    int f  = r & 15;
    const float* wo = Wo_s + s * 256;                 // [e][ep]
    const float* ws = Wsys + s * 2048 + f * 128 + t * 16;  // [e]
    float acc = 0.f;
#pragma unroll
    for (int e = 0; e < 16; ++e)
        acc = fmaf(wo[e * 16 + ep], ws[e], acc);
    g_M[((s * 8 + t) * 16 + ep) * 16 + f] = acc;

    if (idx < 128) {
        int s2 = idx >> 4, f2 = idx & 15;
        float c = bsys[idx];
        const float* wsf = Wsys + s2 * 2048 + f2 * 128;
        const float* bo  = bo_s + s2 * 16;
        for (int k = 0; k < 128; ++k)
            c = fmaf(bo[k & 15], wsf[k], c);
        g_C[idx] = c;
    }
}

// ---------------------------------------------------------------------------
// Attention core for 8 tokens, E=16, H=4. Lane owns head l4 (f = 4*l4..4*l4+3).
// Tokens read from eb[t*16+e]; q-scale pre-folded into weights.
// Output o[t][d] = attention output (before out-proj), register-resident.
// ---------------------------------------------------------------------------
__device__ __forceinline__ void mha_core(const float* __restrict__ sm,
                                         const float* __restrict__ eb,
                                         int wbase, int bbase, int f0,
                                         float o[8][4])
{
    float q[8][4], k[8][4], v[8][4];
    {
        float bq[4], bk[4], bv[4];
        LD4(bq, sm + bbase + f0);
        LD4(bk, sm + bbase + 16 + f0);
        LD4(bv, sm + bbase + 32 + f0);
#pragma unroll
        for (int t = 0; t < 8; ++t)
#pragma unroll
            for (int d = 0; d < 4; ++d) { q[t][d] = bq[d]; k[t][d] = bk[d]; v[t][d] = bv[d]; }
    }
#pragma unroll
    for (int e = 0; e < 16; e += 2) {
        float wqa[4], wka[4], wva[4], wqb[4], wkb[4], wvb[4];
        LD4(wqa, sm + wbase + e * 48 + f0);
        LD4(wka, sm + wbase + e * 48 + 16 + f0);
        LD4(wva, sm + wbase + e * 48 + 32 + f0);
        LD4(wqb, sm + wbase + (e + 1) * 48 + f0);
        LD4(wkb, sm + wbase + (e + 1) * 48 + 16 + f0);
        LD4(wvb, sm + wbase + (e + 1) * 48 + 32 + f0);
#pragma unroll
        for (int t = 0; t < 8; ++t) {
            float2 me = *(const float2*)(eb + t * 16 + e);
#pragma unroll
            for (int d = 0; d < 4; ++d) {
                q[t][d] = fmaf(me.x, wqa[d], fmaf(me.y, wqb[d], q[t][d]));
                k[t][d] = fmaf(me.x, wka[d], fmaf(me.y, wkb[d], k[t][d]));
                v[t][d] = fmaf(me.x, wva[d], fmaf(me.y, wvb[d], v[t][d]));
            }
        }
    }
    // scores + softmax + AV fully in registers (lane = one head)
#pragma unroll
    for (int i = 0; i < 8; ++i) {
        float sc[8];
#pragma unroll
        for (int j = 0; j < 8; ++j)
            sc[j] = fmaf(q[i][0], k[j][0], fmaf(q[i][1], k[j][1],
                    fmaf(q[i][2], k[j][2], q[i][3] * k[j][3])));
        float m = sc[0];
#pragma unroll
        for (int j = 1; j < 8; ++j) m = fmaxf(m, sc[j]);
        float w[8]; float sum = 0.f;
#pragma unroll
        for (int j = 0; j < 8; ++j) { w[j] = __expf(sc[j] - m); sum += w[j]; }
        float inv = __fdividef(1.f, sum);
#pragma unroll
        for (int d = 0; d < 4; ++d) o[i][d] = 0.f;
#pragma unroll
        for (int j = 0; j < 8; ++j) {
            float a = w[j] * inv;
#pragma unroll
            for (int d = 0; d < 4; ++d) o[i][d] = fmaf(a, v[j][d], o[i][d]);
        }
    }
}

// ---------------------------------------------------------------------------
extern "C" __global__ void __launch_bounds__(THREADS_, 1)
bio_encoder_kernel(const float* __restrict__ x,
                   const int*   __restrict__ sys_idx,
                   const float* __restrict__ W1,  const float* __restrict__ b1,
                   const float* __restrict__ W2,  const float* __restrict__ b2,
                   const float* __restrict__ Wqkv_s, const float* __restrict__ bqkv_s,
                   const float* __restrict__ Wqkv_x, const float* __restrict__ bqkv_x,
                   const float* __restrict__ Wo_x,   const float* __restrict__ bo_x,
                   float* __restrict__ out, float* __restrict__ seb)
{
    extern __shared__ float sm[];
    const int tid = threadIdx.x;

    // ---- stage weights (once per block) ----
    for (int i = tid; i < 1024; i += THREADS_) {
        sm[O_W1B1 + 2 * i]     = W1[i];
        sm[O_W1B1 + 2 * i + 1] = b1[i];
    }
    for (int i = tid; i < 16384; i += THREADS_) {      // W2[n][f][e] -> [n][e][f]
        int n = i >> 8, e = (i >> 4) & 15, f = i & 15;
        sm[O_W2T + i] = W2[n * 256 + f * 16 + e];
    }
    for (int i = tid; i < 1024; i += THREADS_) sm[O_B2 + i] = b2[i];
    for (int i = tid; i < 6144; i += THREADS_) {       // Wqkv_s[s][j][e] -> [s][e][j]
        int s = i / 768, r = i - s * 768, e = r / 48, j = r - e * 48;
        float v = Wqkv_s[s * 768 + j * 16 + e];
        if (j < 16) v *= 0.5f;
        sm[O_QKVS + i] = v;
    }
    for (int i = tid; i < 384; i += THREADS_) {
        float v = bqkv_s[i];
        if ((i % 48) < 16) v *= 0.5f;
        sm[O_BQKVS + i] = v;
    }
    for (int i = tid; i < 16384; i += THREADS_) sm[O_MF + i] = g_M[i];
    for (int i = tid; i < 128;   i += THREADS_) sm[O_CF + i] = g_C[i];
    for (int i = tid; i < 768; i += THREADS_) {        // Wqkv_x[j][e] -> [e][j]
        int e = i / 48, j = i - e * 48;
        float v = Wqkv_x[j * 16 + e];
        if (j < 16) v *= 0.5f;
        sm[O_QKVX + i] = v;
    }
    if (tid < 48) { float v = bqkv_x[tid]; if (tid < 16) v *= 0.5f; sm[O_BQKVX + tid] = v; }
    if (tid < 256) {                                   // Wo_x[f][e] -> [e][f]
        int e = tid >> 4, f = tid & 15;
        sm[O_WOX + e * 16 + f] = Wo_x[f * 16 + e];
    }
    if (tid < 16) sm[O_BOX + tid] = bo_x[tid];
    if (tid < 64) ((int*)(sm + O_SIDX))[tid] = sys_idx[tid];
    __syncthreads();

    const int grp = tid >> 2;          // row slot 0..95
    const int f0  = (tid & 3) * 4;     // this lane's 4 f-dims == one head
    float* eb = sm + O_EB + grp * SROW_;
    const int* sidx = (const int*)(sm + O_SIDX);

    for (int tile = blockIdx.x; tile < NTILES_; tile += gridDim.x) {
        int row = tile * ROWS_ + grp;
        const bool wr = row < B_;
        if (!wr) row = B_ - 1;                 // clamp compute; stores predicated
        const float* xr = x + (size_t)row * 64;
        float* serow = seb + (size_t)row * 128;

#pragma unroll 1
        for (int s = 0; s < 8; ++s) {
            // ---- gather this system's x values ----
            float xv[8];
#pragma unroll
            for (int t = 0; t < 8; ++t) xv[t] = xr[sidx[s * 8 + t]];

            // ---- per-biomarker MLP (lane computes its 4 f's) ----
#pragma unroll
            for (int t = 0; t < 8; ++t) {
                const int n = sidx[s * 8 + t];
                float acc[4];
                LD4(acc, sm + O_B2 + n * 16 + f0);
                const float* wb = sm + O_W1B1 + n * 32;
                const float* w2 = sm + O_W2T + n * 256 + f0;
                const float xvt = xv[t];
#pragma unroll
                for (int e = 0; e < 16; ++e) {
                    float2 w = *(const float2*)(wb + 2 * e);
                    float h  = fmaxf(fmaf(w.x, xvt, w.y), 0.f);
                    float ww[4];
                    LD4(ww, w2 + e * 16);
#pragma unroll
                    for (int d = 0; d < 4; ++d) acc[d] = fmaf(h, ww[d], acc[d]);
                }
                ST4(eb + t * 16 + f0, acc);
            }
            __syncwarp();

            // ---- per-system MHA (attention core in registers) ----
            float o[8][4];
            mha_core(sm, eb, O_QKVS + s * 768, O_BQKVS + s * 48, f0, o);
            __syncwarp();                       // everyone done reading eb
#pragma unroll
            for (int t = 0; t < 8; ++t) ST4(eb + t * 16 + f0, o[t]);
            __syncwarp();

            // ---- fused out-proj + system embedding ----
            float accs[4];
            LD4(accs, sm + O_CF + s * 16 + f0);
            const float* mb = sm + O_MF + s * 2048;
#pragma unroll
            for (int t = 0; t < 8; ++t) {
#pragma unroll
                for (int c4 = 0; c4 < 4; ++c4) {
                    float ov[4];
                    LD4(ov, eb + t * 16 + c4 * 4);
#pragma unroll
                    for (int c = 0; c < 4; ++c) {
                        float mw[4];
                        LD4(mw, mb + t * 256 + (c4 * 4 + c) * 16 + f0);
#pragma unroll
                        for (int d = 0; d < 4; ++d)
                            accs[d] = fmaf(ov[c], mw[d], accs[d]);
                    }
                }
            }
            // stream system embedding straight to gmem (all_sys / scratch)
            if (wr) ST4(serow + s * 16 + f0, accs);
            __syncwarp();                       // eb free for next system
        }

        // ---- cross-system MHA: read tokens back (same-thread RAW, L2-hot) ----
#pragma unroll
        for (int s = 0; s < 8; ++s) {
            float sv[4];
            LD4(sv, serow + s * 16 + f0);
            ST4(eb + s * 16 + f0, sv);
        }
        __syncwarp();
        float o[8][4];
        mha_core(sm, eb, O_QKVX, O_BQKVX, f0, o);
        __syncwarp();
#pragma unroll
        for (int t = 0; t < 8; ++t) ST4(eb + t * 16 + f0, o[t]);
        __syncwarp();

        // ---- cross out-proj ----
        float at[8][4];
        {
            float bo[4];
            LD4(bo, sm + O_BOX + f0);
#pragma unroll
            for (int t = 0; t < 8; ++t)
#pragma unroll
                for (int d = 0; d < 4; ++d) at[t][d] = bo[d];
        }
#pragma unroll
        for (int e = 0; e < 16; e += 2) {
            float wa[4], wb2[4];
            LD4(wa,  sm + O_WOX + e * 16 + f0);
            LD4(wb2, sm + O_WOX + (e + 1) * 16 + f0);
#pragma unroll
            for (int t = 0; t < 8; ++t) {
                float2 ov = *(const float2*)(eb + t * 16 + e);
#pragma unroll
                for (int d = 0; d < 4; ++d)
                    at[t][d] = fmaf(ov.x, wa[d], fmaf(ov.y, wb2[d], at[t][d]));
            }
        }
        if (wr) {
#pragma unroll
            for (int t = 0; t < 8; ++t)
                ST4(out + (size_t)row * 128 + t * 16 + f0, at[t]);
        }
        __syncwarp();   // eb reuse next tile
    }
}

extern "C" void kernel_launch(void* const* d_in, const int* in_sizes, int n_in,
                              void* d_out, int out_size) {
    const float* x      = (const float*)d_in[0];
    const int*   sidx   = (const int*)  d_in[1];
    const float* W1     = (const float*)d_in[2];
    const float* b1     = (const float*)d_in[3];
    const float* W2     = (const float*)d_in[4];
    const float* b2     = (const float*)d_in[5];
    const float* Wqkv_s = (const float*)d_in[6];
    const float* bqkv_s = (const float*)d_in[7];
    const float* Wo_s   = (const float*)d_in[8];
    const float* bo_s   = (const float*)d_in[9];
    const float* Wsys   = (const float*)d_in[10];
    const float* bsys   = (const float*)d_in[11];
    const float* Wqkv_x = (const float*)d_in[12];
    const float* bqkv_x = (const float*)d_in[13];
    const float* Wo_x   = (const float*)d_in[14];
    const float* bo_x   = (const float*)d_in[15];
    float* out = (float*)d_out;

    bio_prep_kernel<<<64, 256>>>(Wo_s, Wsys, bo_s, bsys);

    cudaFuncSetAttribute(bio_encoder_kernel,
                         cudaFuncAttributeMaxDynamicSharedMemorySize, SMEM_BYTES);

    // system embeddings stream to the all_sys output region when present,
    // else to a device-global scratch buffer (pure address query; capture-safe)
    float* se_fallback = nullptr;
    cudaGetSymbolAddress((void**)&se_fallback, g_SE);
    float* seb = (out_size >= 2 * B_ * 128) ? (out + (size_t)B_ * 128) : se_fallback;

    bio_encoder_kernel<<<GRID_, THREADS_, SMEM_BYTES>>>(
        x, sidx, W1, b1, W2, b2, Wqkv_s, bqkv_s,
        Wqkv_x, bqkv_x, Wo_x, bo_x, out, seb);
}

// round 11
// speedup vs baseline: 1.0871x; 1.0871x over previous
#include <cuda_runtime.h>
#include <cuda_bf16.h>

// Problem constants
#define B_   65536
#define NS_  8
#define G_   8
#define E_   16

#define THREADS_ 256
#define ROWS_    64            // rows per tile (4 threads per row)
#define NTILES_  (B_ / ROWS_)  // 1024
#define GRID_    152

// ---- shared memory layout (float offsets) ----
#define O_W1B1  0        // [n][e]{W1,b1}                2048
#define O_W2T   2048     // [n][e][f]                    16384
#define O_B2    18432    // [n][f]                       1024
#define O_QKVS  19456    // [s][e][48]  (q-part *0.5)    6144
#define O_BQKVS 25600    // [s][48]     (q-part *0.5)    384
#define O_MF    25984    // [s][t][ep][f] fused Wo*Wsys  16384
#define O_CF    42368    // [s][f]                       128
#define O_QKVX  42496    // [e][48]     (q-part *0.5)    768
#define O_BQKVX 43264    // [48]        (q-part *0.5)    48
#define O_WOX   43312    // [e][f]                       256
#define O_BOX   43568    // [f]                          16
#define O_SIDX  43584    // 64 ints                      64
#define O_EB    43648    // 64 rows x SROW token scratch
#define SROW_   132      // 132*4B = 528B, 16B-aligned per row
#define SMEM_FLOATS (O_EB + ROWS_ * SROW_)   // 52096
#define SMEM_BYTES  (SMEM_FLOATS * 4)        // 208384

typedef unsigned long long u64;
typedef ulonglong2 u64x2;

// fused out-proj * system-embedding weights (per-launch precompute)
__device__ float g_M[NS_ * G_ * E_ * E_];   // [s][t][ep][f]
__device__ float g_C[NS_ * E_];             // [s][f]

#define LD4(dst, p) { float4 _t = *(const float4*)(p); \
    (dst)[0]=_t.x; (dst)[1]=_t.y; (dst)[2]=_t.z; (dst)[3]=_t.w; }

// ---- packed f32x2 helpers (sm_103a; ptxas never auto-fuses these) ----
__device__ __forceinline__ u64 f2fma(u64 a, u64 b, u64 c) {
    u64 d; asm("fma.rn.f32x2 %0, %1, %2, %3;" : "=l"(d) : "l"(a), "l"(b), "l"(c)); return d;
}
__device__ __forceinline__ u64 f2mul(u64 a, u64 b) {
    u64 d; asm("mul.rn.f32x2 %0, %1, %2;" : "=l"(d) : "l"(a), "l"(b)); return d;
}
__device__ __forceinline__ u64 dup2(float x) {
    u64 d; unsigned r = __float_as_uint(x);
    asm("mov.b64 %0, {%1, %2};" : "=l"(d) : "r"(r), "r"(r)); return d;
}
__device__ __forceinline__ float2 unpk2(u64 v) {
    unsigned lo, hi; asm("mov.b64 {%0, %1}, %2;" : "=r"(lo), "=r"(hi) : "l"(v));
    return make_float2(__uint_as_float(lo), __uint_as_float(hi));
}
__device__ __forceinline__ u64x2 lds2(const float* p) { return *(const u64x2*)p; }
__device__ __forceinline__ void sts2(float* p, u64 a, u64 b) {
    u64x2 t; t.x = a; t.y = b; *(u64x2*)p = t;
}

// ---------------------------------------------------------------------------
// Prep: M[s][t][ep][f] = sum_e Wo_s[s][e][ep] * Wsys[s][f][t*16+e]
//       C[s][f]        = bsys[s][f] + sum_{t,e} bo_s[s][e]*Wsys[s][f][t*16+e]
// ---------------------------------------------------------------------------
__global__ void bio_prep_kernel(const float* __restrict__ Wo_s,
                                const float* __restrict__ Wsys,
                                const float* __restrict__ bo_s,
                                const float* __restrict__ bsys)
{
    int idx = blockIdx.x * blockDim.x + threadIdx.x;   // 0..16383
    int s  = idx >> 11;
    int r  = idx & 2047;
    int t  = r >> 8;
    int ep = (r >> 4) & 15;
    int f  = r & 15;
    const float* wo = Wo_s + s * 256;                       // [e][ep]
    const float* ws = Wsys + s * 2048 + f * 128 + t * 16;   // [e]
    float acc = 0.f;
#pragma unroll
    for (int e = 0; e < 16; ++e)
        acc = fmaf(wo[e * 16 + ep], ws[e], acc);
    g_M[((s * 8 + t) * 16 + ep) * 16 + f] = acc;

    if (idx < 128) {
        int s2 = idx >> 4, f2 = idx & 15;
        float c = bsys[idx];
        const float* wsf = Wsys + s2 * 2048 + f2 * 128;
        const float* bo  = bo_s + s2 * 16;
        for (int k = 0; k < 128; ++k)
            c = fmaf(bo[k & 15], wsf[k], c);
        g_C[idx] = c;
    }
}

// ---------------------------------------------------------------------------
// Attention core, packed. Lane owns one head (f = f0..f0+3 as two f32x2).
// Tokens in eb[t*16+e]; q-scale pre-folded. Outputs o01/o23[t] packed.
// ---------------------------------------------------------------------------
__device__ __forceinline__ void mha_core(const float* __restrict__ sm,
                                         const float* __restrict__ eb,
                                         int wbase, int bbase, int f0,
                                         u64 o01[8], u64 o23[8])
{
    u64 q01[8], q23[8], k01[8], k23[8], v01[8], v23[8];
    {
        u64x2 BQ = lds2(sm + bbase + f0);
        u64x2 BK = lds2(sm + bbase + 16 + f0);
        u64x2 BV = lds2(sm + bbase + 32 + f0);
#pragma unroll
        for (int t = 0; t < 8; ++t) {
            q01[t] = BQ.x; q23[t] = BQ.y;
            k01[t] = BK.x; k23[t] = BK.y;
            v01[t] = BV.x; v23[t] = BV.y;
        }
    }
#pragma unroll
    for (int e = 0; e < 16; e += 2) {
        u64x2 WQa = lds2(sm + wbase + e * 48 + f0);
        u64x2 WKa = lds2(sm + wbase + e * 48 + 16 + f0);
        u64x2 WVa = lds2(sm + wbase + e * 48 + 32 + f0);
        u64x2 WQb = lds2(sm + wbase + (e + 1) * 48 + f0);
        u64x2 WKb = lds2(sm + wbase + (e + 1) * 48 + 16 + f0);
        u64x2 WVb = lds2(sm + wbase + (e + 1) * 48 + 32 + f0);
#pragma unroll
        for (int t = 0; t < 8; ++t) {
            float2 me = *(const float2*)(eb + t * 16 + e);
            u64 mex = dup2(me.x), mey = dup2(me.y);
            q01[t] = f2fma(mex, WQa.x, f2fma(mey, WQb.x, q01[t]));
            q23[t] = f2fma(mex, WQa.y, f2fma(mey, WQb.y, q23[t]));
            k01[t] = f2fma(mex, WKa.x, f2fma(mey, WKb.x, k01[t]));
            k23[t] = f2fma(mex, WKa.y, f2fma(mey, WKb.y, k23[t]));
            v01[t] = f2fma(mex, WVa.x, f2fma(mey, WVb.x, v01[t]));
            v23[t] = f2fma(mex, WVa.y, f2fma(mey, WVb.y, v23[t]));
        }
    }
    // scores + softmax + AV in registers (lane = one head)
#pragma unroll
    for (int i = 0; i < 8; ++i) {
        float sc[8];
#pragma unroll
        for (int j = 0; j < 8; ++j) {
            u64 p = f2mul(q01[i], k01[j]);
            p = f2fma(q23[i], k23[j], p);
            float2 pf = unpk2(p);
            sc[j] = pf.x + pf.y;
        }
        float m = sc[0];
#pragma unroll
        for (int j = 1; j < 8; ++j) m = fmaxf(m, sc[j]);
        float w[8]; float sum = 0.f;
#pragma unroll
        for (int j = 0; j < 8; ++j) { w[j] = __expf(sc[j] - m); sum += w[j]; }
        float inv = __fdividef(1.f, sum);
        u64 a01 = 0ull, a23 = 0ull;
#pragma unroll
        for (int j = 0; j < 8; ++j) {
            u64 ap = dup2(w[j] * inv);
            a01 = f2fma(ap, v01[j], a01);
            a23 = f2fma(ap, v23[j], a23);
        }
        o01[i] = a01; o23[i] = a23;
    }
}

// ---------------------------------------------------------------------------
extern "C" __global__ void __launch_bounds__(THREADS_, 1)
bio_encoder_kernel(const float* __restrict__ x,
                   const int*   __restrict__ sys_idx,
                   const float* __restrict__ W1,  const float* __restrict__ b1,
                   const float* __restrict__ W2,  const float* __restrict__ b2,
                   const float* __restrict__ Wqkv_s, const float* __restrict__ bqkv_s,
                   const float* __restrict__ Wqkv_x, const float* __restrict__ bqkv_x,
                   const float* __restrict__ Wo_x,   const float* __restrict__ bo_x,
                   float* __restrict__ out, int write_all_sys)
{
    extern __shared__ float sm[];
    const int tid = threadIdx.x;

    // ---- stage weights (once per block) ----
    for (int i = tid; i < 1024; i += THREADS_) {
        sm[O_W1B1 + 2 * i]     = W1[i];
        sm[O_W1B1 + 2 * i + 1] = b1[i];
    }
    for (int i = tid; i < 16384; i += THREADS_) {      // W2[n][f][e] -> [n][e][f]
        int n = i >> 8, e = (i >> 4) & 15, f = i & 15;
        sm[O_W2T + i] = W2[n * 256 + f * 16 + e];
    }
    for (int i = tid; i < 1024; i += THREADS_) sm[O_B2 + i] = b2[i];
    for (int i = tid; i < 6144; i += THREADS_) {       // Wqkv_s[s][j][e] -> [s][e][j]
        int s = i / 768, r = i - s * 768, e = r / 48, j = r - e * 48;
        float v = Wqkv_s[s * 768 + j * 16 + e];
        if (j < 16) v *= 0.5f;
        sm[O_QKVS + i] = v;
    }
    for (int i = tid; i < 384; i += THREADS_) {
        float v = bqkv_s[i];
        if ((i % 48) < 16) v *= 0.5f;
        sm[O_BQKVS + i] = v;
    }
    for (int i = tid; i < 16384; i += THREADS_) sm[O_MF + i] = g_M[i];
    for (int i = tid; i < 128;   i += THREADS_) sm[O_CF + i] = g_C[i];
    for (int i = tid; i < 768; i += THREADS_) {        // Wqkv_x[j][e] -> [e][j]
        int e = i / 48, j = i - e * 48;
        float v = Wqkv_x[j * 16 + e];
        if (j < 16) v *= 0.5f;
        sm[O_QKVX + i] = v;
    }
    if (tid < 48) { float v = bqkv_x[tid]; if (tid < 16) v *= 0.5f; sm[O_BQKVX + tid] = v; }
    if (tid < 256) {                                   // Wo_x[f][e] -> [e][f]
        int e = tid >> 4, f = tid & 15;
        sm[O_WOX + e * 16 + f] = Wo_x[f * 16 + e];
    }
    if (tid < 16) sm[O_BOX + tid] = bo_x[tid];
    if (tid < 64) ((int*)(sm + O_SIDX))[tid] = sys_idx[tid];
    __syncthreads();

    const int grp = tid >> 2;          // row slot 0..63
    const int f0  = (tid & 3) * 4;     // this lane's 4 f-dims == one head
    float* eb = sm + O_EB + grp * SROW_;
    const int* sidx = (const int*)(sm + O_SIDX);

    for (int tile = blockIdx.x; tile < NTILES_; tile += gridDim.x) {
        const int row = tile * ROWS_ + grp;
        const float* xr = x + (size_t)row * 64;

        u64 se01[8], se23[8];

#pragma unroll 1
        for (int s = 0; s < 8; ++s) {
            // ---- gather this system's x values ----
            float xv[8];
#pragma unroll
            for (int t = 0; t < 8; ++t) xv[t] = xr[sidx[s * 8 + t]];

            // ---- per-biomarker MLP (packed over this lane's 4 f's) ----
#pragma unroll
            for (int t = 0; t < 8; ++t) {
                const int n = sidx[s * 8 + t];
                u64x2 ACC = lds2(sm + O_B2 + n * 16 + f0);
                u64 a01 = ACC.x, a23 = ACC.y;
                const float* wb = sm + O_W1B1 + n * 32;
                const float* w2 = sm + O_W2T + n * 256 + f0;
                const float xvt = xv[t];
#pragma unroll
                for (int e = 0; e < 16; ++e) {
                    float2 w = *(const float2*)(wb + 2 * e);
                    float h  = fmaxf(fmaf(w.x, xvt, w.y), 0.f);
                    u64 hh = dup2(h);
                    u64x2 W2v = lds2(w2 + e * 16);
                    a01 = f2fma(hh, W2v.x, a01);
                    a23 = f2fma(hh, W2v.y, a23);
                }
                sts2(eb + t * 16 + f0, a01, a23);
            }
            __syncwarp();

            // ---- per-system MHA (packed attention core) ----
            u64 o01[8], o23[8];
            mha_core(sm, eb, O_QKVS + s * 768, O_BQKVS + s * 48, f0, o01, o23);
            __syncwarp();                       // everyone done reading eb
#pragma unroll
            for (int t = 0; t < 8; ++t) sts2(eb + t * 16 + f0, o01[t], o23[t]);
            __syncwarp();

            // ---- fused out-proj + system embedding ----
            u64x2 C = lds2(sm + O_CF + s * 16 + f0);
            u64 s01 = C.x, s23 = C.y;
            const float* mb = sm + O_MF + s * 2048;
#pragma unroll
            for (int t = 0; t < 8; ++t) {
#pragma unroll
                for (int c4 = 0; c4 < 4; ++c4) {
                    float ov[4];
                    LD4(ov, eb + t * 16 + c4 * 4);
#pragma unroll
                    for (int c = 0; c < 4; ++c) {
                        u64 op = dup2(ov[c]);
                        u64x2 MW = lds2(mb + t * 256 + (c4 * 4 + c) * 16 + f0);
                        s01 = f2fma(op, MW.x, s01);
                        s23 = f2fma(op, MW.y, s23);
                    }
                }
            }
            se01[s] = s01; se23[s] = s23;
            __syncwarp();                       // eb free for next system
        }

        // ---- all_sys output ----
        if (write_all_sys) {
#pragma unroll
            for (int s = 0; s < 8; ++s)
                sts2(out + (size_t)B_ * 128 + (size_t)row * 128 + s * 16 + f0,
                     se01[s], se23[s]);
        }

        // ---- cross-system MHA ----
#pragma unroll
        for (int s = 0; s < 8; ++s) sts2(eb + s * 16 + f0, se01[s], se23[s]);
        __syncwarp();
        u64 o01[8], o23[8];
        mha_core(sm, eb, O_QKVX, O_BQKVX, f0, o01, o23);
        __syncwarp();
#pragma unroll
        for (int t = 0; t < 8; ++t) sts2(eb + t * 16 + f0, o01[t], o23[t]);
        __syncwarp();

        // ---- cross out-proj (packed) ----
        u64 at01[8], at23[8];
        {
            u64x2 BO = lds2(sm + O_BOX + f0);
#pragma unroll
            for (int t = 0; t < 8; ++t) { at01[t] = BO.x; at23[t] = BO.y; }
        }
#pragma unroll
        for (int e = 0; e < 16; e += 2) {
            u64x2 WA = lds2(sm + O_WOX + e * 16 + f0);
            u64x2 WB = lds2(sm + O_WOX + (e + 1) * 16 + f0);
#pragma unroll
            for (int t = 0; t < 8; ++t) {
                float2 me = *(const float2*)(eb + t * 16 + e);
                u64 mex = dup2(me.x), mey = dup2(me.y);
                at01[t] = f2fma(mex, WA.x, f2fma(mey, WB.x, at01[t]));
                at23[t] = f2fma(mex, WA.y, f2fma(mey, WB.y, at23[t]));
            }
        }
#pragma unroll
        for (int t = 0; t < 8; ++t)
            sts2(out + (size_t)row * 128 + t * 16 + f0, at01[t], at23[t]);
        __syncwarp();   // eb reuse next tile
    }
}

extern "C" void kernel_launch(void* const* d_in, const int* in_sizes, int n_in,
                              void* d_out, int out_size) {
    const float* x      = (const float*)d_in[0];
    const int*   sidx   = (const int*)  d_in[1];
    const float* W1     = (const float*)d_in[2];
    const float* b1     = (const float*)d_in[3];
    const float* W2     = (const float*)d_in[4];
    const float* b2     = (const float*)d_in[5];
    const float* Wqkv_s = (const float*)d_in[6];
    const float* bqkv_s = (const float*)d_in[7];
    const float* Wo_s   = (const float*)d_in[8];
    const float* bo_s   = (const float*)d_in[9];
    const float* Wsys   = (const float*)d_in[10];
    const float* bsys   = (const float*)d_in[11];
    const float* Wqkv_x = (const float*)d_in[12];
    const float* bqkv_x = (const float*)d_in[13];
    const float* Wo_x   = (const float*)d_in[14];
    const float* bo_x   = (const float*)d_in[15];
    float* out = (float*)d_out;

    bio_prep_kernel<<<64, 256>>>(Wo_s, Wsys, bo_s, bsys);

    cudaFuncSetAttribute(bio_encoder_kernel,
                         cudaFuncAttributeMaxDynamicSharedMemorySize, SMEM_BYTES);

    int write_all_sys = (out_size >= 2 * B_ * 128) ? 1 : 0;

    bio_encoder_kernel<<<GRID_, THREADS_, SMEM_BYTES>>>(
        x, sidx, W1, b1, W2, b2, Wqkv_s, bqkv_s,
        Wqkv_x, bqkv_x, Wo_x, bo_x, out, write_all_sys);
}

// round 12
// speedup vs baseline: 1.2312x; 1.1326x over previous
#include <cuda_runtime.h>
#include <cuda_bf16.h>

// Problem constants
#define B_   65536
#define NS_  8
#define G_   8
#define E_   16

#define THREADS_ 256
#define ROWS_    64            // rows per tile (4 threads per row)
#define NTILES_  (B_ / ROWS_)  // 1024
#define GRID_    152

// ---- shared memory layout (float offsets) ----
// W2T and MF now live in GLOBAL memory (L1D-cached) to offload the smem crossbar.
#define O_W1B1  0        // [n][e]{W1,b1}                2048
#define O_B2    2048     // [n][f]                       1024
#define O_QKVS  3072     // [s][e][48]  (q-part *0.5)    6144
#define O_BQKVS 9216     // [s][48]     (q-part *0.5)    384
#define O_CF    9600     // [s][f]                       128
#define O_QKVX  9728     // [e][48]     (q-part *0.5)    768
#define O_BQKVX 10496    // [48]        (q-part *0.5)    48
#define O_WOX   10544    // [e][f]                       256
#define O_BOX   10800    // [f]                          16
#define O_SIDX  10816    // 64 ints                      64
#define O_EB    10880    // 64 rows x SROW token scratch
#define SROW_   132      // 132*4B = 528B, 16B-aligned per row
#define SMEM_FLOATS (O_EB + ROWS_ * SROW_)   // 19328
#define SMEM_BYTES  (SMEM_FLOATS * 4)        // 77312

typedef unsigned long long u64;
typedef ulonglong2 u64x2;

// global weight streams (read through L1D; row-invariant broadcasts)
__device__ __align__(16) float g_M[NS_ * G_ * E_ * E_];    // [s][t][ep][f]
__device__ __align__(16) float g_C[NS_ * E_];              // [s][f]
__device__ __align__(16) float g_W2T[64 * E_ * E_];        // [n][e][f]

#define LD4(dst, p) { float4 _t = *(const float4*)(p); \
    (dst)[0]=_t.x; (dst)[1]=_t.y; (dst)[2]=_t.z; (dst)[3]=_t.w; }

// ---- packed f32x2 helpers (sm_103a; ptxas never auto-fuses these) ----
__device__ __forceinline__ u64 f2fma(u64 a, u64 b, u64 c) {
    u64 d; asm("fma.rn.f32x2 %0, %1, %2, %3;" : "=l"(d) : "l"(a), "l"(b), "l"(c)); return d;
}
__device__ __forceinline__ u64 f2mul(u64 a, u64 b) {
    u64 d; asm("mul.rn.f32x2 %0, %1, %2;" : "=l"(d) : "l"(a), "l"(b)); return d;
}
__device__ __forceinline__ u64 dup2(float x) {
    u64 d; unsigned r = __float_as_uint(x);
    asm("mov.b64 %0, {%1, %2};" : "=l"(d) : "r"(r), "r"(r)); return d;
}
__device__ __forceinline__ float2 unpk2(u64 v) {
    unsigned lo, hi; asm("mov.b64 {%0, %1}, %2;" : "=r"(lo), "=r"(hi) : "l"(v));
    return make_float2(__uint_as_float(lo), __uint_as_float(hi));
}
__device__ __forceinline__ u64x2 lds2(const float* p) { return *(const u64x2*)p; }
__device__ __forceinline__ u64x2 ldg2(const float* __restrict__ p) { return *(const u64x2*)p; }
__device__ __forceinline__ void sts2(float* p, u64 a, u64 b) {
    u64x2 t; t.x = a; t.y = b; *(u64x2*)p = t;
}

// ---------------------------------------------------------------------------
// Prep: g_W2T[n][e][f] = W2[n][f][e]
//       M[s][t][ep][f] = sum_e Wo_s[s][e][ep] * Wsys[s][f][t*16+e]
//       C[s][f]        = bsys[s][f] + sum_{t,e} bo_s[s][e]*Wsys[s][f][t*16+e]
// ---------------------------------------------------------------------------
__global__ void bio_prep_kernel(const float* __restrict__ Wo_s,
                                const float* __restrict__ Wsys,
                                const float* __restrict__ bo_s,
                                const float* __restrict__ bsys,
                                const float* __restrict__ W2)
{
    int idx = blockIdx.x * blockDim.x + threadIdx.x;   // 0..16383
    int s  = idx >> 11;
    int r  = idx & 2047;
    int t  = r >> 8;
    int ep = (r >> 4) & 15;
    int f  = r & 15;
    const float* wo = Wo_s + s * 256;                       // [e][ep]
    const float* ws = Wsys + s * 2048 + f * 128 + t * 16;   // [e]
    float acc = 0.f;
#pragma unroll
    for (int e = 0; e < 16; ++e)
        acc = fmaf(wo[e * 16 + ep], ws[e], acc);
    g_M[((s * 8 + t) * 16 + ep) * 16 + f] = acc;

    // W2 transpose: [n][f][e] -> [n][e][f]
    {
        int n = idx >> 8, e2 = (idx >> 4) & 15, f2 = idx & 15;
        g_W2T[idx] = W2[n * 256 + f2 * 16 + e2];
    }

    if (idx < 128) {
        int s2 = idx >> 4, f2 = idx & 15;
        float c = bsys[idx];
        const float* wsf = Wsys + s2 * 2048 + f2 * 128;
        const float* bo  = bo_s + s2 * 16;
        for (int k = 0; k < 128; ++k)
            c = fmaf(bo[k & 15], wsf[k], c);
        g_C[idx] = c;
    }
}

// ---------------------------------------------------------------------------
// Attention core, packed. Lane owns one head (f = f0..f0+3 as two f32x2).
// ---------------------------------------------------------------------------
__device__ __forceinline__ void mha_core(const float* __restrict__ sm,
                                         const float* __restrict__ eb,
                                         int wbase, int bbase, int f0,
                                         u64 o01[8], u64 o23[8])
{
    u64 q01[8], q23[8], k01[8], k23[8], v01[8], v23[8];
    {
        u64x2 BQ = lds2(sm + bbase + f0);
        u64x2 BK = lds2(sm + bbase + 16 + f0);
        u64x2 BV = lds2(sm + bbase + 32 + f0);
#pragma unroll
        for (int t = 0; t < 8; ++t) {
            q01[t] = BQ.x; q23[t] = BQ.y;
            k01[t] = BK.x; k23[t] = BK.y;
            v01[t] = BV.x; v23[t] = BV.y;
        }
    }
#pragma unroll
    for (int e = 0; e < 16; e += 2) {
        u64x2 WQa = lds2(sm + wbase + e * 48 + f0);
        u64x2 WKa = lds2(sm + wbase + e * 48 + 16 + f0);
        u64x2 WVa = lds2(sm + wbase + e * 48 + 32 + f0);
        u64x2 WQb = lds2(sm + wbase + (e + 1) * 48 + f0);
        u64x2 WKb = lds2(sm + wbase + (e + 1) * 48 + 16 + f0);
        u64x2 WVb = lds2(sm + wbase + (e + 1) * 48 + 32 + f0);
#pragma unroll
        for (int t = 0; t < 8; ++t) {
            float2 me = *(const float2*)(eb + t * 16 + e);
            u64 mex = dup2(me.x), mey = dup2(me.y);
            q01[t] = f2fma(mex, WQa.x, f2fma(mey, WQb.x, q01[t]));
            q23[t] = f2fma(mex, WQa.y, f2fma(mey, WQb.y, q23[t]));
            k01[t] = f2fma(mex, WKa.x, f2fma(mey, WKb.x, k01[t]));
            k23[t] = f2fma(mex, WKa.y, f2fma(mey, WKb.y, k23[t]));
            v01[t] = f2fma(mex, WVa.x, f2fma(mey, WVb.x, v01[t]));
            v23[t] = f2fma(mex, WVa.y, f2fma(mey, WVb.y, v23[t]));
        }
    }
#pragma unroll
    for (int i = 0; i < 8; ++i) {
        float sc[8];
#pragma unroll
        for (int j = 0; j < 8; ++j) {
            u64 p = f2mul(q01[i], k01[j]);
            p = f2fma(q23[i], k23[j], p);
            float2 pf = unpk2(p);
            sc[j] = pf.x + pf.y;
        }
        float m = sc[0];
#pragma unroll
        for (int j = 1; j < 8; ++j) m = fmaxf(m, sc[j]);
        float w[8]; float sum = 0.f;
#pragma unroll
        for (int j = 0; j < 8; ++j) { w[j] = __expf(sc[j] - m); sum += w[j]; }
        float inv = __fdividef(1.f, sum);
        u64 a01 = 0ull, a23 = 0ull;
#pragma unroll
        for (int j = 0; j < 8; ++j) {
            u64 ap = dup2(w[j] * inv);
            a01 = f2fma(ap, v01[j], a01);
            a23 = f2fma(ap, v23[j], a23);
        }
        o01[i] = a01; o23[i] = a23;
    }
}

// ---------------------------------------------------------------------------
extern "C" __global__ void __launch_bounds__(THREADS_, 1)
bio_encoder_kernel(const float* __restrict__ x,
                   const int*   __restrict__ sys_idx,
                   const float* __restrict__ W1,  const float* __restrict__ b1,
                   const float* __restrict__ b2,
                   const float* __restrict__ Wqkv_s, const float* __restrict__ bqkv_s,
                   const float* __restrict__ Wqkv_x, const float* __restrict__ bqkv_x,
                   const float* __restrict__ Wo_x,   const float* __restrict__ bo_x,
                   float* __restrict__ out, int write_all_sys)
{
    extern __shared__ float sm[];
    const int tid = threadIdx.x;

    // ---- stage small weights into shared (W2T and MF stay in gmem/L1D) ----
    for (int i = tid; i < 1024; i += THREADS_) {
        sm[O_W1B1 + 2 * i]     = W1[i];
        sm[O_W1B1 + 2 * i + 1] = b1[i];
    }
    for (int i = tid; i < 1024; i += THREADS_) sm[O_B2 + i] = b2[i];
    for (int i = tid; i < 6144; i += THREADS_) {       // Wqkv_s[s][j][e] -> [s][e][j]
        int s = i / 768, r = i - s * 768, e = r / 48, j = r - e * 48;
        float v = Wqkv_s[s * 768 + j * 16 + e];
        if (j < 16) v *= 0.5f;
        sm[O_QKVS + i] = v;
    }
    for (int i = tid; i < 384; i += THREADS_) {
        float v = bqkv_s[i];
        if ((i % 48) < 16) v *= 0.5f;
        sm[O_BQKVS + i] = v;
    }
    for (int i = tid; i < 128; i += THREADS_) sm[O_CF + i] = g_C[i];
    for (int i = tid; i < 768; i += THREADS_) {        // Wqkv_x[j][e] -> [e][j]
        int e = i / 48, j = i - e * 48;
        float v = Wqkv_x[j * 16 + e];
        if (j < 16) v *= 0.5f;
        sm[O_QKVX + i] = v;
    }
    if (tid < 48) { float v = bqkv_x[tid]; if (tid < 16) v *= 0.5f; sm[O_BQKVX + tid] = v; }
    if (tid < 256) {                                   // Wo_x[f][e] -> [e][f]
        int e = tid >> 4, f = tid & 15;
        sm[O_WOX + e * 16 + f] = Wo_x[f * 16 + e];
    }
    if (tid < 16) sm[O_BOX + tid] = bo_x[tid];
    if (tid < 64) ((int*)(sm + O_SIDX))[tid] = sys_idx[tid];
    __syncthreads();

    const int grp = tid >> 2;          // row slot 0..63
    const int f0  = (tid & 3) * 4;     // this lane's 4 f-dims == one head
    float* eb = sm + O_EB + grp * SROW_;
    const int* sidx = (const int*)(sm + O_SIDX);

    for (int tile = blockIdx.x; tile < NTILES_; tile += gridDim.x) {
        const int row = tile * ROWS_ + grp;
        const float* xr = x + (size_t)row * 64;

        u64 se01[8], se23[8];

#pragma unroll 1
        for (int s = 0; s < 8; ++s) {
            float xv[8];
#pragma unroll
            for (int t = 0; t < 8; ++t) xv[t] = xr[sidx[s * 8 + t]];

            // ---- per-biomarker MLP (W2 streamed from gmem/L1D) ----
#pragma unroll
            for (int t = 0; t < 8; ++t) {
                const int n = sidx[s * 8 + t];
                u64x2 ACC = lds2(sm + O_B2 + n * 16 + f0);
                u64 a01 = ACC.x, a23 = ACC.y;
                const float* wb = sm + O_W1B1 + n * 32;
                const float* __restrict__ w2 = g_W2T + n * 256 + f0;
                const float xvt = xv[t];
#pragma unroll
                for (int e = 0; e < 16; ++e) {
                    float2 w = *(const float2*)(wb + 2 * e);
                    float h  = fmaxf(fmaf(w.x, xvt, w.y), 0.f);
                    u64 hh = dup2(h);
                    u64x2 W2v = ldg2(w2 + e * 16);
                    a01 = f2fma(hh, W2v.x, a01);
                    a23 = f2fma(hh, W2v.y, a23);
                }
                sts2(eb + t * 16 + f0, a01, a23);
            }
            __syncwarp();

            // ---- per-system MHA ----
            u64 o01[8], o23[8];
            mha_core(sm, eb, O_QKVS + s * 768, O_BQKVS + s * 48, f0, o01, o23);
            __syncwarp();
#pragma unroll
            for (int t = 0; t < 8; ++t) sts2(eb + t * 16 + f0, o01[t], o23[t]);
            __syncwarp();

            // ---- fused out-proj + system embedding (M streamed from gmem/L1D) ----
            u64x2 C = lds2(sm + O_CF + s * 16 + f0);
            u64 s01 = C.x, s23 = C.y;
            const float* __restrict__ mb = g_M + s * 2048;
#pragma unroll
            for (int t = 0; t < 8; ++t) {
#pragma unroll
                for (int c4 = 0; c4 < 4; ++c4) {
                    float ov[4];
                    LD4(ov, eb + t * 16 + c4 * 4);
#pragma unroll
                    for (int c = 0; c < 4; ++c) {
                        u64 op = dup2(ov[c]);
                        u64x2 MW = ldg2(mb + t * 256 + (c4 * 4 + c) * 16 + f0);
                        s01 = f2fma(op, MW.x, s01);
                        s23 = f2fma(op, MW.y, s23);
                    }
                }
            }
            se01[s] = s01; se23[s] = s23;
            __syncwarp();
        }

        // ---- all_sys output ----
        if (write_all_sys) {
#pragma unroll
            for (int s = 0; s < 8; ++s)
                sts2(out + (size_t)B_ * 128 + (size_t)row * 128 + s * 16 + f0,
                     se01[s], se23[s]);
        }

        // ---- cross-system MHA ----
#pragma unroll
        for (int s = 0; s < 8; ++s) sts2(eb + s * 16 + f0, se01[s], se23[s]);
        __syncwarp();
        u64 o01[8], o23[8];
        mha_core(sm, eb, O_QKVX, O_BQKVX, f0, o01, o23);
        __syncwarp();
#pragma unroll
        for (int t = 0; t < 8; ++t) sts2(eb + t * 16 + f0, o01[t], o23[t]);
        __syncwarp();

        // ---- cross out-proj (packed) ----
        u64 at01[8], at23[8];
        {
            u64x2 BO = lds2(sm + O_BOX + f0);
#pragma unroll
            for (int t = 0; t < 8; ++t) { at01[t] = BO.x; at23[t] = BO.y; }
        }
#pragma unroll
        for (int e = 0; e < 16; e += 2) {
            u64x2 WA = lds2(sm + O_WOX + e * 16 + f0);
            u64x2 WB = lds2(sm + O_WOX + (e + 1) * 16 + f0);
#pragma unroll
            for (int t = 0; t < 8; ++t) {
                float2 me = *(const float2*)(eb + t * 16 + e);
                u64 mex = dup2(me.x), mey = dup2(me.y);
                at01[t] = f2fma(mex, WA.x, f2fma(mey, WB.x, at01[t]));
                at23[t] = f2fma(mex, WA.y, f2fma(mey, WB.y, at23[t]));
            }
        }
#pragma unroll
        for (int t = 0; t < 8; ++t)
            sts2(out + (size_t)row * 128 + t * 16 + f0, at01[t], at23[t]);
        __syncwarp();
    }
}

extern "C" void kernel_launch(void* const* d_in, const int* in_sizes, int n_in,
                              void* d_out, int out_size) {
    const float* x      = (const float*)d_in[0];
    const int*   sidx   = (const int*)  d_in[1];
    const float* W1     = (const float*)d_in[2];
    const float* b1     = (const float*)d_in[3];
    const float* W2     = (const float*)d_in[4];
    const float* b2     = (const float*)d_in[5];
    const float* Wqkv_s = (const float*)d_in[6];
    const float* bqkv_s = (const float*)d_in[7];
    const float* Wo_s   = (const float*)d_in[8];
    const float* bo_s   = (const float*)d_in[9];
    const float* Wsys   = (const float*)d_in[10];
    const float* bsys   = (const float*)d_in[11];
    const float* Wqkv_x = (const float*)d_in[12];
    const float* bqkv_x = (const float*)d_in[13];
    const float* Wo_x   = (const float*)d_in[14];
    const float* bo_x   = (const float*)d_in[15];
    float* out = (float*)d_out;

    bio_prep_kernel<<<64, 256>>>(Wo_s, Wsys, bo_s, bsys, W2);

    cudaFuncSetAttribute(bio_encoder_kernel,
                         cudaFuncAttributeMaxDynamicSharedMemorySize, SMEM_BYTES);

    int write_all_sys = (out_size >= 2 * B_ * 128) ? 1 : 0;

    bio_encoder_kernel<<<GRID_, THREADS_, SMEM_BYTES>>>(
        x, sidx, W1, b1, b2, Wqkv_s, bqkv_s,
        Wqkv_x, bqkv_x, Wo_x, bo_x, out, write_all_sys);
}